// round 4
// baseline (speedup 1.0000x reference)
#include <cuda_runtime.h>

#define NU 50000
#define NI 50000
#define NN 100000            // NU + NI
#define D  64
#define K  4
#define E  1000000
#define NTOT (K * NN)        // 400000
#define TOTE (K * 2 * E)     // 8M directed edges
#define SCAN_CHUNK 1024
#define NB_SCAN ((NTOT + SCAN_CHUNK - 1) / SCAN_CHUNK)   // 391

#define TILE_E 128           // rows per epilogue block
#define SPAD   68            // smem row pad (floats), float4-aligned

// f32x2 packed FMA helpers
#define FFMA2(acc, a, b) \
    asm("fma.rn.f32x2 %0, %1, %2, %0;" : "+l"(acc) : "l"(a), "l"(b))
#define PACK2(dst, lo, hi) \
    asm("mov.b64 %0, {%1, %2};" : "=l"(dst) : "f"(lo), "f"(hi))

__device__ __forceinline__ float lo_f(unsigned long long v) {
    return __uint_as_float((unsigned)(v & 0xffffffffull));
}
__device__ __forceinline__ float hi_f(unsigned long long v) {
    return __uint_as_float((unsigned)(v >> 32));
}
__device__ __forceinline__ float tanhf_fast(float x) {
    float y;
    asm("tanh.approx.f32 %0, %1;" : "=f"(y) : "f"(x));
    return y;
}

// ---------------- device scratch -------------------------------------------
__device__ int   g_deg[NTOT];
__device__ int   g_rowptr[NTOT + 1];
__device__ int   g_cursor[NTOT];
__device__ int   g_col[TOTE];
__device__ float g_dinv[NTOT];
__device__ float g_xc[NN * D];      // current x
__device__ float g_g[NN * D];       // spmm1 operand, then node_pre
__device__ float g_gnext[NN * D];   // dinv ⊙ edge (spmm2 operand)
__device__ float g_node[NN * D];    // fc1 output
__device__ int   g_partials[NB_SCAN];

// ---------------- CSR build (unchanged, proven) ------------------------------
__global__ void count_deg_kernel(const int* __restrict__ rows,
                                 const int* __restrict__ cols) {
    int idx = blockIdx.x * blockDim.x + threadIdx.x;
    if (idx >= K * E) return;
    int base = (idx / E) * NN;
    atomicAdd(g_deg + base + rows[idx], 1);
    atomicAdd(g_deg + base + NU + cols[idx], 1);
}

__global__ void scan_s1_kernel() {
    __shared__ int red[256];
    int tid = threadIdx.x;
    int base = blockIdx.x * SCAN_CHUNK + tid * 4;
    int s = 0;
#pragma unroll
    for (int j = 0; j < 4; j++)
        if (base + j < NTOT) s += g_deg[base + j];
    red[tid] = s;
    __syncthreads();
    for (int off = 128; off; off >>= 1) {
        if (tid < off) red[tid] += red[tid + off];
        __syncthreads();
    }
    if (tid == 0) g_partials[blockIdx.x] = red[0];
}

__global__ void scan_s2_kernel() {
    __shared__ int sh[512];
    int tid = threadIdx.x;
    int v = (tid < NB_SCAN) ? g_partials[tid] : 0;
    sh[tid] = v;
    __syncthreads();
    for (int off = 1; off < 512; off <<= 1) {
        int t = (tid >= off) ? sh[tid - off] : 0;
        __syncthreads();
        sh[tid] += t;
        __syncthreads();
    }
    if (tid < NB_SCAN) g_partials[tid] = sh[tid] - v;
}

__global__ void scan_s3_kernel() {
    __shared__ int warp_sums[8];
    int tid = threadIdx.x;
    int lane = tid & 31, warp = tid >> 5;
    int base = blockIdx.x * SCAN_CHUNK + tid * 4;
    int e[4];
    int s = 0;
#pragma unroll
    for (int j = 0; j < 4; j++) {
        e[j] = (base + j < NTOT) ? g_deg[base + j] : 0;
        s += e[j];
    }
    int incl = s;
#pragma unroll
    for (int off = 1; off < 32; off <<= 1) {
        int t = __shfl_up_sync(0xffffffffu, incl, off);
        if (lane >= off) incl += t;
    }
    if (lane == 31) warp_sums[warp] = incl;
    __syncthreads();
    if (warp == 0 && lane < 8) {
        int v = warp_sums[lane];
        int iv = v;
#pragma unroll
        for (int off = 1; off < 8; off <<= 1) {
            int t = __shfl_up_sync(0xffu, iv, off);
            if (lane >= off) iv += t;
        }
        warp_sums[lane] = iv - v;
    }
    __syncthreads();
    int run = g_partials[blockIdx.x] + warp_sums[warp] + (incl - s);
#pragma unroll
    for (int j = 0; j < 4; j++) {
        int idx = base + j;
        if (idx < NTOT) {
            g_rowptr[idx] = run;
            g_cursor[idx] = run;
            g_dinv[idx]   = rsqrtf((float)e[j] + 1e-7f);
            run += e[j];
        }
    }
    if (blockIdx.x == 0 && tid == 0) g_rowptr[NTOT] = TOTE;
}

__global__ void fill_csr_kernel(const int* __restrict__ rows,
                                const int* __restrict__ cols) {
    int idx = blockIdx.x * blockDim.x + threadIdx.x;
    if (idx >= K * E) return;
    int base = (idx / E) * NN;
    int r = rows[idx];
    int c = cols[idx];
    int p1 = atomicAdd(g_cursor + base + r, 1);
    g_col[p1] = NU + c;
    int p2 = atomicAdd(g_cursor + base + NU + c, 1);
    g_col[p2] = r;
}

// ---------------- g = dinv ⊙ (relu(xc) + bias)  (step 0 only) ----------------
__global__ void compute_g_kernel(const float* __restrict__ bias, int k) {
    int idx = blockIdx.x * blockDim.x + threadIdx.x;
    if (idx >= NN * 16) return;
    int i = idx >> 4;
    int q = (idx & 15) << 2;
    float di = g_dinv[k * NN + i];
    float4 x = *(const float4*)(g_xc + i * D + q);
    float4 b = *(const float4*)(bias + q);
    float4 o;
    o.x = di * (fmaxf(x.x, 0.f) + b.x);
    o.y = di * (fmaxf(x.y, 0.f) + b.y);
    o.z = di * (fmaxf(x.z, 0.f) + b.z);
    o.w = di * (fmaxf(x.w, 0.f) + b.w);
    *(float4*)(g_g + i * D + q) = o;
}

// ---------------- spmm gather: warp per row, float4 lanes, 2 nbrs/iter -------
// out1[i] = dinv[i] * sum_{n} src[n];  if out2: out2[i] = dinv[i] * out1[i]
__global__ void spmm_kernel(const float* __restrict__ src,
                            float* __restrict__ out1,
                            float* __restrict__ out2, int k) {
    int gw = (blockIdx.x * blockDim.x + threadIdx.x) >> 5;
    if (gw >= NN) return;
    int lane = threadIdx.x & 31;
    int q    = (lane & 15) << 2;
    int half = lane >> 4;
    int rp = k * NN + gw;
    int beg = g_rowptr[rp], end = g_rowptr[rp + 1];

    float4 acc = make_float4(0.f, 0.f, 0.f, 0.f);
    int p = beg + half;
    // 8 neighbors per warp iteration (4 per half), 4 LDG.128 in flight per lane
    for (; p + 6 < end; p += 8) {
        int n0 = __ldg(g_col + p);
        int n1 = __ldg(g_col + p + 2);
        int n2 = __ldg(g_col + p + 4);
        int n3 = __ldg(g_col + p + 6);
        float4 v0 = *(const float4*)(src + n0 * D + q);
        float4 v1 = *(const float4*)(src + n1 * D + q);
        float4 v2 = *(const float4*)(src + n2 * D + q);
        float4 v3 = *(const float4*)(src + n3 * D + q);
        acc.x += (v0.x + v1.x) + (v2.x + v3.x);
        acc.y += (v0.y + v1.y) + (v2.y + v3.y);
        acc.z += (v0.z + v1.z) + (v2.z + v3.z);
        acc.w += (v0.w + v1.w) + (v2.w + v3.w);
    }
    for (; p < end; p += 2) {
        int n = __ldg(g_col + p);
        float4 v = *(const float4*)(src + n * D + q);
        acc.x += v.x; acc.y += v.y; acc.z += v.z; acc.w += v.w;
    }
    // combine the two halves
    acc.x += __shfl_xor_sync(0xffffffffu, acc.x, 16);
    acc.y += __shfl_xor_sync(0xffffffffu, acc.y, 16);
    acc.z += __shfl_xor_sync(0xffffffffu, acc.z, 16);
    acc.w += __shfl_xor_sync(0xffffffffu, acc.w, 16);

    if (half == 0) {
        float di = g_dinv[rp];
        float4 e = make_float4(di * acc.x, di * acc.y, di * acc.z, di * acc.w);
        *(float4*)(out1 + (size_t)gw * D + q) = e;
        if (out2)
            *(float4*)(out2 + (size_t)gw * D + q) =
                make_float4(di * e.x, di * e.y, di * e.z, di * e.w);
    }
}

// ---------------- fc1: softmax(node_pre) @ fc1_W^T  (thread per row) ---------
// dynamic smem: Wt[4096] | S[TILE_E*SPAD]
__global__ void __launch_bounds__(128)
fc1_kernel(const float* __restrict__ fc1_W) {
    extern __shared__ float sh[];
    float* Wt = sh;                 // Wt[d*64+j] = fc1_W[j][d]
    float* S  = sh + 4096;

    int tid = threadIdx.x;
    for (int i = tid; i < 4096; i += 128) {
        int d = i >> 6, j = i & 63;
        Wt[i] = fc1_W[j * 64 + d];
    }

    int base = blockIdx.x * TILE_E;
    int warp = tid >> 5, lane = tid & 31;
    int lane2 = lane * 2;

    // phase 1: warp-per-row softmax of node_pre (g_g), store rows into S
    for (int i = 0; i < 32; i++) {
        int rl = warp * 32 + i;
        int row = base + rl;
        if (row >= NN) break;
        float2 v = *(const float2*)(g_g + (size_t)row * D + lane2);
        float m = fmaxf(v.x, v.y);
#pragma unroll
        for (int o = 16; o; o >>= 1) m = fmaxf(m, __shfl_xor_sync(0xffffffffu, m, o));
        float e0 = __expf(v.x - m), e1 = __expf(v.y - m);
        float s = e0 + e1;
#pragma unroll
        for (int o = 16; o; o >>= 1) s += __shfl_xor_sync(0xffffffffu, s, o);
        float inv = 1.0f / s;
        S[rl * SPAD + lane2]     = e0 * inv;
        S[rl * SPAD + lane2 + 1] = e1 * inv;
    }
    __syncthreads();

    // phase 2: thread-per-row GEMV with packed f32x2 accumulators
    int rl = tid;
    int row = base + rl;
    if (row < NN) {
        unsigned long long acc[32];
#pragma unroll
        for (int a = 0; a < 32; a++) acc[a] = 0ull;
        const ulonglong2* Wp = (const ulonglong2*)Wt;
#pragma unroll 2
        for (int d = 0; d < 64; d++) {
            float sv = S[rl * SPAD + d];
            unsigned long long sp;
            PACK2(sp, sv, sv);
            const ulonglong2* wrow = Wp + d * 16;
#pragma unroll
            for (int jj = 0; jj < 16; jj++) {
                ulonglong2 w = wrow[jj];
                FFMA2(acc[jj * 2],     sp, w.x);
                FFMA2(acc[jj * 2 + 1], sp, w.y);
            }
        }
        // stash result into own S row (no cross-thread hazard)
#pragma unroll
        for (int a = 0; a < 32; a++) {
            S[rl * SPAD + 2 * a]     = lo_f(acc[a]);
            S[rl * SPAD + 2 * a + 1] = hi_f(acc[a]);
        }
    }
    __syncthreads();

    // coalesced write of node
    for (int i = tid; i < TILE_E * 16; i += 128) {
        int r = i >> 4;
        int q = (i & 15) << 2;
        int grow = base + r;
        if (grow < NN)
            *(float4*)(g_node + (size_t)grow * D + q) = *(const float4*)(S + r * SPAD + q);
    }
}

// ---------------- fusion gate + fused compute_g for next step ----------------
// dynamic smem: Wt[4096] | X[TILE_E*SPAD] | NB[TILE_E*SPAD]
__global__ void __launch_bounds__(128)
fusion_kernel(const float* __restrict__ W1,
              const float* __restrict__ b1,
              const float* __restrict__ w2,
              const float* __restrict__ hbias,
              float* __restrict__ out_nodes, int knext) {
    extern __shared__ float sh[];
    float* Wt = sh;
    float* X  = sh + 4096;
    float* NB = X + TILE_E * SPAD;
    __shared__ float b1s[64], w2s[64], biass[64], avals[TILE_E];

    int tid = threadIdx.x;
    for (int i = tid; i < 4096; i += 128) {
        int d = i >> 6, j = i & 63;
        Wt[i] = W1[j * 64 + d];
    }
    if (tid < 64) {
        b1s[tid]   = b1[tid];
        w2s[tid]   = w2[tid];
        biass[tid] = hbias[tid];
    }

    int base = blockIdx.x * TILE_E;
    int warp = tid >> 5, lane = tid & 31;
    int lane2 = lane * 2;

    // phase 1: stage x and node rows into smem
    for (int i = 0; i < 32; i++) {
        int rl = warp * 32 + i;
        int row = base + rl;
        if (row >= NN) break;
        float2 vx = *(const float2*)(g_xc   + (size_t)row * D + lane2);
        float2 vn = *(const float2*)(g_node + (size_t)row * D + lane2);
        X[rl * SPAD + lane2]      = vx.x;
        X[rl * SPAD + lane2 + 1]  = vx.y;
        NB[rl * SPAD + lane2]     = vn.x;
        NB[rl * SPAD + lane2 + 1] = vn.y;
    }
    __syncthreads();

    // phase 2: thread-per-row double GEMV (hidden_x, hidden_n)
    int rl = tid;
    int row = base + rl;
    if (row < NN) {
        unsigned long long hx[32], hn[32];
#pragma unroll
        for (int a = 0; a < 32; a++) { hx[a] = 0ull; hn[a] = 0ull; }
        const ulonglong2* Wp = (const ulonglong2*)Wt;
#pragma unroll 2
        for (int d = 0; d < 64; d++) {
            float xv = X[rl * SPAD + d];
            float nv = NB[rl * SPAD + d];
            unsigned long long xp, np;
            PACK2(xp, xv, xv);
            PACK2(np, nv, nv);
            const ulonglong2* wrow = Wp + d * 16;
#pragma unroll
            for (int jj = 0; jj < 16; jj++) {
                ulonglong2 w = wrow[jj];
                FFMA2(hx[jj * 2],     xp, w.x);
                FFMA2(hx[jj * 2 + 1], xp, w.y);
                FFMA2(hn[jj * 2],     np, w.x);
                FFMA2(hn[jj * 2 + 1], np, w.y);
            }
        }
        float sx = 0.f, sn = 0.f;
#pragma unroll
        for (int a = 0; a < 32; a++) {
            float bx0 = b1s[2 * a], bx1 = b1s[2 * a + 1];
            float w0  = w2s[2 * a], w1  = w2s[2 * a + 1];
            sx += tanhf_fast(lo_f(hx[a]) + bx0) * w0 + tanhf_fast(hi_f(hx[a]) + bx1) * w1;
            sn += tanhf_fast(lo_f(hn[a]) + bx0) * w0 + tanhf_fast(hi_f(hn[a]) + bx1) * w1;
        }
        // 2-way softmax -> alpha on x branch
        avals[rl] = 1.0f / (1.0f + __expf(sn - sx));
    }
    __syncthreads();

    // phase 3: coalesced blend + outputs (+ fused compute_g for next step)
    for (int i = tid; i < TILE_E * 16; i += 128) {
        int r = i >> 4;
        int q = (i & 15) << 2;
        int grow = base + r;
        if (grow >= NN) continue;
        float a = avals[r];
        float4 xv = *(const float4*)(X  + r * SPAD + q);
        float4 nv = *(const float4*)(NB + r * SPAD + q);
        float4 o;
        o.x = a * xv.x + (1.f - a) * nv.x;
        o.y = a * xv.y + (1.f - a) * nv.y;
        o.z = a * xv.z + (1.f - a) * nv.z;
        o.w = a * xv.w + (1.f - a) * nv.w;
        *(float4*)(out_nodes + (size_t)grow * D + q) = o;
        *(float4*)(g_xc + (size_t)grow * D + q) = o;
        if (knext >= 0) {
            float di = __ldg(g_dinv + knext * NN + grow);
            float4 b = *(const float4*)(biass + q);
            float4 g;
            g.x = di * (fmaxf(o.x, 0.f) + b.x);
            g.y = di * (fmaxf(o.y, 0.f) + b.y);
            g.z = di * (fmaxf(o.z, 0.f) + b.z);
            g.w = di * (fmaxf(o.w, 0.f) + b.w);
            *(float4*)(g_g + (size_t)grow * D + q) = g;
        }
    }
}

// ---------------- launch ------------------------------------------------------
extern "C" void kernel_launch(void* const* d_in, const int* in_sizes, int n_in,
                              void* d_out, int out_size) {
    const float* x         = (const float*)d_in[0];
    const float* hgc1_bias = (const float*)d_in[1];
    const float* fc1_W     = (const float*)d_in[2];
    const float* fus_l1_W  = (const float*)d_in[3];
    const float* fus_l1_b  = (const float*)d_in[4];
    const float* fus_l2_W  = (const float*)d_in[5];
    // d_in[6] = fus_l2_b : cancels in the 2-way softmax
    const int* rows = (const int*)d_in[7];
    const int* cols = (const int*)d_in[8];

    float* out_nodes = (float*)d_out;
    float* out_edges = (float*)d_out + (size_t)K * NN * D;

    float *xc_p = nullptr, *g_p = nullptr, *gn_p = nullptr;
    int* deg_p = nullptr;
    cudaGetSymbolAddress((void**)&xc_p, g_xc);
    cudaGetSymbolAddress((void**)&g_p, g_g);
    cudaGetSymbolAddress((void**)&gn_p, g_gnext);
    cudaGetSymbolAddress((void**)&deg_p, g_deg);

    static int smem_set = 0;
    const int FC1_SMEM = (4096 + TILE_E * SPAD) * 4;                // 51200
    const int FUS_SMEM = (4096 + 2 * TILE_E * SPAD) * 4;            // 86016
    if (!smem_set) {
        cudaFuncSetAttribute(fc1_kernel,
                             cudaFuncAttributeMaxDynamicSharedMemorySize, FC1_SMEM);
        cudaFuncSetAttribute(fusion_kernel,
                             cudaFuncAttributeMaxDynamicSharedMemorySize, FUS_SMEM);
        smem_set = 1;
    }

    // CSR build (depends only on rows/cols)
    cudaMemsetAsync(deg_p, 0, (size_t)NTOT * sizeof(int));
    count_deg_kernel<<<(K * E + 255) / 256, 256>>>(rows, cols);
    scan_s1_kernel<<<NB_SCAN, 256>>>();
    scan_s2_kernel<<<1, 512>>>();
    scan_s3_kernel<<<NB_SCAN, 256>>>();
    fill_csr_kernel<<<(K * E + 255) / 256, 256>>>(rows, cols);

    cudaMemcpyAsync(xc_p, x, (size_t)NN * D * sizeof(float),
                    cudaMemcpyDeviceToDevice);

    const int ELT_BLOCKS  = (NN * 16 + 255) / 256;      // 6250
    const int SPMM_BLOCKS = NN / 8;                      // 12500 (warp/row)
    const int EPI_BLOCKS  = (NN + TILE_E - 1) / TILE_E;  // 782

    compute_g_kernel<<<ELT_BLOCKS, 256>>>(hgc1_bias, 0);

    for (int k = 0; k < K; k++) {
        float* edge_k = out_edges + (size_t)k * NN * D;
        // spmm1: edge = Â g ; gnext = dinv ⊙ edge
        spmm_kernel<<<SPMM_BLOCKS, 256>>>(g_p, edge_k, gn_p, k);
        // spmm2: node_pre = Â (dinv ⊙ edge)  -> g_g
        spmm_kernel<<<SPMM_BLOCKS, 256>>>(gn_p, g_p, nullptr, k);
        fc1_kernel<<<EPI_BLOCKS, 128, FC1_SMEM>>>(fc1_W);
        fusion_kernel<<<EPI_BLOCKS, 128, FUS_SMEM>>>(
            fus_l1_W, fus_l1_b, fus_l2_W, hgc1_bias,
            out_nodes + (size_t)k * NN * D, (k + 1 < K) ? (k + 1) : -1);
    }
}

// round 5
// speedup vs baseline: 1.0452x; 1.0452x over previous
#include <cuda_runtime.h>
#include <cuda_fp16.h>

#define NU 50000
#define NI 50000
#define NN 100000            // NU + NI
#define D  64
#define K  4
#define E  1000000
#define NTOT (K * NN)        // 400000
#define TOTE (K * 2 * E)     // 8M directed edges
#define SCAN_CHUNK 1024
#define NB_SCAN ((NTOT + SCAN_CHUNK - 1) / SCAN_CHUNK)   // 391

__device__ __forceinline__ float tanhf_fast(float x) {
    float y;
    asm("tanh.approx.f32 %0, %1;" : "=f"(y) : "f"(x));
    return y;
}

// ---------------- device scratch (zero-init at load; g_deg restored by s3) ---
__device__ int    g_deg[NTOT];
__device__ int    g_rowptr[NTOT + 1];
__device__ int    g_cursor[NTOT];
__device__ int    g_col[TOTE];
__device__ float  g_dinv[NTOT];
__device__ float  g_xc[NN * D];      // current x fp32 (gate/output path)
__device__ __half g_xh[NN * D];      // current x fp16 (spmm1 gather operand)
__device__ __half g_eh[NN * D];      // dinv ⊙ edge fp16 (spmm2 gather operand)
__device__ float  g_g[NN * D];       // node_pre fp32 (mega input)
__device__ int    g_partials[NB_SCAN];

// ---------------- CSR build --------------------------------------------------
__global__ void count_deg_kernel(const int* __restrict__ rows,
                                 const int* __restrict__ cols) {
    int idx = blockIdx.x * blockDim.x + threadIdx.x;
    if (idx >= K * E) return;
    int base = (idx / E) * NN;
    atomicAdd(g_deg + base + rows[idx], 1);
    atomicAdd(g_deg + base + NU + cols[idx], 1);
}

__global__ void scan_s1_kernel() {
    __shared__ int red[256];
    int tid = threadIdx.x;
    int base = blockIdx.x * SCAN_CHUNK + tid * 4;
    int s = 0;
#pragma unroll
    for (int j = 0; j < 4; j++)
        if (base + j < NTOT) s += g_deg[base + j];
    red[tid] = s;
    __syncthreads();
    for (int off = 128; off; off >>= 1) {
        if (tid < off) red[tid] += red[tid + off];
        __syncthreads();
    }
    if (tid == 0) g_partials[blockIdx.x] = red[0];
}

// s3: per-block prefix over g_partials (inline), local scan, write rowptr/
// cursor/dinv, and RE-ZERO g_deg so the next launch starts clean.
__global__ void scan_s3_kernel() {
    __shared__ int warp_sums[8];
    __shared__ int pred_red[8];
    int tid = threadIdx.x;
    int lane = tid & 31, warp = tid >> 5;

    // inline "lookback": sum of partials of preceding blocks
    int ps = 0;
    for (int i = tid; i < blockIdx.x; i += 256) ps += g_partials[i];
#pragma unroll
    for (int off = 16; off; off >>= 1) ps += __shfl_xor_sync(0xffffffffu, ps, off);
    if (lane == 0) pred_red[warp] = ps;
    __syncthreads();
    int block_prefix = 0;
#pragma unroll
    for (int w = 0; w < 8; w++) block_prefix += pred_red[w];

    int base = blockIdx.x * SCAN_CHUNK + tid * 4;
    int e[4];
    int s = 0;
#pragma unroll
    for (int j = 0; j < 4; j++) {
        e[j] = (base + j < NTOT) ? g_deg[base + j] : 0;
        s += e[j];
    }
    int incl = s;
#pragma unroll
    for (int off = 1; off < 32; off <<= 1) {
        int t = __shfl_up_sync(0xffffffffu, incl, off);
        if (lane >= off) incl += t;
    }
    if (lane == 31) warp_sums[warp] = incl;
    __syncthreads();
    if (warp == 0 && lane < 8) {
        int v = warp_sums[lane];
        int iv = v;
#pragma unroll
        for (int off = 1; off < 8; off <<= 1) {
            int t = __shfl_up_sync(0xffu, iv, off);
            if (lane >= off) iv += t;
        }
        warp_sums[lane] = iv - v;
    }
    __syncthreads();
    int run = block_prefix + warp_sums[warp] + (incl - s);
#pragma unroll
    for (int j = 0; j < 4; j++) {
        int idx = base + j;
        if (idx < NTOT) {
            g_rowptr[idx] = run;
            g_cursor[idx] = run;
            g_dinv[idx]   = rsqrtf((float)e[j] + 1e-7f);
            g_deg[idx]    = 0;              // restore for next launch
            run += e[j];
        }
    }
    if (blockIdx.x == 0 && tid == 0) g_rowptr[NTOT] = TOTE;
}

__global__ void fill_csr_kernel(const int* __restrict__ rows,
                                const int* __restrict__ cols) {
    int idx = blockIdx.x * blockDim.x + threadIdx.x;
    if (idx >= K * E) return;
    int base = (idx / E) * NN;
    int r = rows[idx];
    int c = cols[idx];
    int p1 = atomicAdd(g_cursor + base + r, 1);
    g_col[p1] = NU + c;
    int p2 = atomicAdd(g_cursor + base + NU + c, 1);
    g_col[p2] = r;
}

// ---------------- generic CSR gather -----------------------------------------
// TRANSFORM: per-neighbor operand = dinv[n] * (relu(src[n]) + bias)   (spmm1)
// else     : operand = src[n]                                          (spmm2)
// out_f32[i] = dinv[i] * sum(operands);  out_h (if non-null) = dinv[i]*out_f32[i]
// Warp per row; lanes split in two halves of 16; each lane owns 4 features.
template<bool SRC_HALF, bool TRANSFORM>
__global__ void __launch_bounds__(256)
gather_kernel(const void* __restrict__ src,
              const float* __restrict__ bias,
              float* __restrict__ out_f32,
              __half* __restrict__ out_h, int k) {
    int gw = (blockIdx.x * blockDim.x + threadIdx.x) >> 5;
    if (gw >= NN) return;
    int lane = threadIdx.x & 31;
    int sub  = lane & 15;
    int half_id = lane >> 4;
    int f = sub << 2;                     // feature base, 4 floats per lane
    int rp = k * NN + gw;
    int beg = g_rowptr[rp], end = g_rowptr[rp + 1];
    const float* dv = g_dinv + k * NN;

    float4 b4 = make_float4(0.f, 0.f, 0.f, 0.f);
    if (TRANSFORM) b4 = *(const float4*)(bias + f);

    const float*  sf = (const float*)src;
    const __half* sh = (const __half*)src;

    float4 acc = make_float4(0.f, 0.f, 0.f, 0.f);

#define LOADV(vv, n)                                                       \
    do {                                                                   \
        if (SRC_HALF) {                                                    \
            uint2 raw = *(const uint2*)(sh + (size_t)(n) * D + f);         \
            float2 lo = __half22float2(*(const __half2*)&raw.x);           \
            float2 hi = __half22float2(*(const __half2*)&raw.y);           \
            vv = make_float4(lo.x, lo.y, hi.x, hi.y);                      \
        } else {                                                           \
            vv = *(const float4*)(sf + (size_t)(n) * D + f);               \
        }                                                                  \
    } while (0)

#define ACCUM(vv, n)                                                       \
    do {                                                                   \
        if (TRANSFORM) {                                                   \
            float dn = __ldg(dv + (n));                                    \
            acc.x += dn * (fmaxf(vv.x, 0.f) + b4.x);                       \
            acc.y += dn * (fmaxf(vv.y, 0.f) + b4.y);                       \
            acc.z += dn * (fmaxf(vv.z, 0.f) + b4.z);                       \
            acc.w += dn * (fmaxf(vv.w, 0.f) + b4.w);                       \
        } else {                                                           \
            acc.x += vv.x; acc.y += vv.y; acc.z += vv.z; acc.w += vv.w;    \
        }                                                                  \
    } while (0)

    int p = beg + half_id;
    for (; p + 6 < end; p += 8) {
        int n0 = __ldg(g_col + p);
        int n1 = __ldg(g_col + p + 2);
        int n2 = __ldg(g_col + p + 4);
        int n3 = __ldg(g_col + p + 6);
        float4 v0, v1, v2, v3;
        LOADV(v0, n0); LOADV(v1, n1); LOADV(v2, n2); LOADV(v3, n3);
        ACCUM(v0, n0); ACCUM(v1, n1); ACCUM(v2, n2); ACCUM(v3, n3);
    }
    for (; p < end; p += 2) {
        int n = __ldg(g_col + p);
        float4 v;
        LOADV(v, n);
        ACCUM(v, n);
    }
#undef LOADV
#undef ACCUM

    acc.x += __shfl_xor_sync(0xffffffffu, acc.x, 16);
    acc.y += __shfl_xor_sync(0xffffffffu, acc.y, 16);
    acc.z += __shfl_xor_sync(0xffffffffu, acc.z, 16);
    acc.w += __shfl_xor_sync(0xffffffffu, acc.w, 16);

    if (half_id == 0) {
        float di = dv[gw];
        float4 e = make_float4(di * acc.x, di * acc.y, di * acc.z, di * acc.w);
        *(float4*)(out_f32 + (size_t)gw * D + f) = e;
        if (out_h) {
            __half2 h01 = __floats2half2_rn(di * e.x, di * e.y);
            __half2 h23 = __floats2half2_rn(di * e.z, di * e.w);
            uint2 raw;
            raw.x = *(const unsigned*)&h01;
            raw.y = *(const unsigned*)&h23;
            *(uint2*)(out_h + (size_t)gw * D + f) = raw;
        }
    }
}

// ---------------- mega epilogue: softmax + fc1 + fusion gate ------------------
// Warp per row, grid-stride; weights staged in smem once per block.
__global__ void __launch_bounds__(256)
mega_kernel(const float* __restrict__ fc1_W,
            const float* __restrict__ W1,
            const float* __restrict__ b1,
            const float* __restrict__ w2,
            const float* __restrict__ xc_src,
            float* __restrict__ out_nodes) {
    __shared__ float Wt1[64 * 64];   // Wt1[d*64+j] = fc1_W[j][d]
    __shared__ float Wtf[64 * 64];
    __shared__ float b1s[64], w2s[64];
    __shared__ float smv[8][64];
    __shared__ float xb[8][64];
    __shared__ float nb[8][64];

    int tid = threadIdx.x;
    for (int i = tid; i < 4096; i += 256) {
        int d = i >> 6, j = i & 63;
        Wt1[i] = fc1_W[j * 64 + d];
        Wtf[i] = W1[j * 64 + d];
    }
    if (tid < 64) { b1s[tid] = b1[tid]; w2s[tid] = w2[tid]; }
    __syncthreads();

    int warp = tid >> 5, lane = tid & 31;
    int lane2 = lane * 2;

    for (int row = blockIdx.x * 8 + warp; row < NN; row += gridDim.x * 8) {
        // node_pre (already dinv-scaled) from g_g
        float2 v = *(const float2*)(g_g + (size_t)row * D + lane2);
        float ax = v.x, ay = v.y;

        float m = fmaxf(ax, ay);
#pragma unroll
        for (int o = 16; o; o >>= 1) m = fmaxf(m, __shfl_xor_sync(0xffffffffu, m, o));
        float e0 = __expf(ax - m), e1 = __expf(ay - m);
        float ssum = e0 + e1;
#pragma unroll
        for (int o = 16; o; o >>= 1) ssum += __shfl_xor_sync(0xffffffffu, ssum, o);
        float inv = 1.0f / ssum;
        smv[warp][lane2]     = e0 * inv;
        smv[warp][lane2 + 1] = e1 * inv;

        float2 vx = *(const float2*)(xc_src + (size_t)row * D + lane2);
        xb[warp][lane2]     = vx.x;
        xb[warp][lane2 + 1] = vx.y;
        __syncwarp();

        float n0 = 0.f, n1 = 0.f;
#pragma unroll
        for (int d = 0; d < 64; d++) {
            float sv = smv[warp][d];
            float2 w = *(const float2*)(&Wt1[d * 64 + lane2]);
            n0 += sv * w.x;
            n1 += sv * w.y;
        }
        nb[warp][lane2]     = n0;
        nb[warp][lane2 + 1] = n1;
        __syncwarp();

        float ax0 = b1s[lane2], ax1 = b1s[lane2 + 1];
        float an0 = ax0, an1 = ax1;
#pragma unroll
        for (int d = 0; d < 64; d++) {
            float2 w = *(const float2*)(&Wtf[d * 64 + lane2]);
            float ex = xb[warp][d], en = nb[warp][d];
            ax0 += ex * w.x;
            ax1 += ex * w.y;
            an0 += en * w.x;
            an1 += en * w.y;
        }
        float sx = tanhf_fast(ax0) * w2s[lane2] + tanhf_fast(ax1) * w2s[lane2 + 1];
        float sn = tanhf_fast(an0) * w2s[lane2] + tanhf_fast(an1) * w2s[lane2 + 1];
#pragma unroll
        for (int o = 16; o; o >>= 1) {
            sx += __shfl_xor_sync(0xffffffffu, sx, o);
            sn += __shfl_xor_sync(0xffffffffu, sn, o);
        }
        float a = 1.0f / (1.0f + __expf(sn - sx));

        float o0 = a * vx.x + (1.f - a) * n0;
        float o1 = a * vx.y + (1.f - a) * n1;
        *(float2*)(out_nodes + (size_t)row * D + lane2) = make_float2(o0, o1);
        *(float2*)(g_xc + (size_t)row * D + lane2)      = make_float2(o0, o1);
        __half2 oh = __floats2half2_rn(o0, o1);
        *(__half2*)(g_xh + (size_t)row * D + lane2)     = oh;
    }
}

// ---------------- launch ------------------------------------------------------
extern "C" void kernel_launch(void* const* d_in, const int* in_sizes, int n_in,
                              void* d_out, int out_size) {
    const float* x         = (const float*)d_in[0];
    const float* hgc1_bias = (const float*)d_in[1];
    const float* fc1_W     = (const float*)d_in[2];
    const float* fus_l1_W  = (const float*)d_in[3];
    const float* fus_l1_b  = (const float*)d_in[4];
    const float* fus_l2_W  = (const float*)d_in[5];
    // d_in[6] = fus_l2_b : cancels in the 2-way softmax
    const int* rows = (const int*)d_in[7];
    const int* cols = (const int*)d_in[8];

    float* out_nodes = (float*)d_out;
    float* out_edges = (float*)d_out + (size_t)K * NN * D;

    float *xc_p = nullptr, *g_p = nullptr;
    __half *xh_p = nullptr, *eh_p = nullptr;
    cudaGetSymbolAddress((void**)&xc_p, g_xc);
    cudaGetSymbolAddress((void**)&xh_p, g_xh);
    cudaGetSymbolAddress((void**)&eh_p, g_eh);
    cudaGetSymbolAddress((void**)&g_p, g_g);

    // CSR build: 4 kernel launches (g_deg re-zeroed inside scan_s3)
    count_deg_kernel<<<(K * E + 255) / 256, 256>>>(rows, cols);
    scan_s1_kernel<<<NB_SCAN, 256>>>();
    scan_s3_kernel<<<NB_SCAN, 256>>>();
    fill_csr_kernel<<<(K * E + 255) / 256, 256>>>(rows, cols);

    const int SPMM_BLOCKS = NN / 8;     // 12500 (warp per row)
    const int MEGA_BLOCKS = 740;

    for (int k = 0; k < K; k++) {
        float* edge_k = out_edges + (size_t)k * NN * D;
        const float* xc_src = (k == 0) ? x : xc_p;
        // spmm1: edge = Â h(xc);  g_eh = dinv ⊙ edge  (fp16)
        if (k == 0)
            gather_kernel<false, true><<<SPMM_BLOCKS, 256>>>(
                (const void*)x, hgc1_bias, edge_k, eh_p, k);
        else
            gather_kernel<true, true><<<SPMM_BLOCKS, 256>>>(
                (const void*)xh_p, hgc1_bias, edge_k, eh_p, k);
        // spmm2: node_pre = Â (dinv ⊙ edge)  -> g_g (fp32)
        gather_kernel<true, false><<<SPMM_BLOCKS, 256>>>(
            (const void*)eh_p, nullptr, g_p, nullptr, k);
        // epilogue: softmax + fc1 + fusion gate; writes out_nodes, g_xc, g_xh
        mega_kernel<<<MEGA_BLOCKS, 256>>>(fc1_W, fus_l1_W, fus_l1_b, fus_l2_W,
                                          xc_src,
                                          out_nodes + (size_t)k * NN * D);
    }
}